// round 7
// baseline (speedup 1.0000x reference)
#include <cuda_runtime.h>

#define ULL unsigned long long

__device__ float g_Qp[256 * 9216];
__device__ float g_V[9216 * 64];     // V[p][c]
__device__ float g_cA[8 * 256];
__device__ float g_cB[256];
__device__ float g_cC[256];

__device__ __forceinline__ ULL pack2(float lo, float hi) {
    ULL r;
    asm("mov.b64 %0, {%1, %2};" : "=l"(r)
        : "r"(__float_as_uint(lo)), "r"(__float_as_uint(hi)));
    return r;
}
__device__ __forceinline__ void unpack2(ULL v, float& lo, float& hi) {
    unsigned a, b;
    asm("mov.b64 {%0, %1}, %2;" : "=r"(a), "=r"(b) : "l"(v));
    lo = __uint_as_float(a);
    hi = __uint_as_float(b);
}
__device__ __forceinline__ void fma2(ULL& d, ULL a, ULL b) {
    asm("fma.rn.f32x2 %0, %1, %2, %0;" : "+l"(d) : "l"(a), "l"(b));
}
__device__ __forceinline__ void mul2(ULL& d, ULL a) {
    asm("mul.rn.f32x2 %0, %0, %1;" : "+l"(d) : "l"(a));
}

#define HBAR(id) asm volatile("bar.sync %0, 256;" :: "r"(id) : "memory")

// ---------------- kernel 1: per-feature coefficients ----------------
__global__ void coef_kernel(const float* __restrict__ WQ_task,
                            const float* __restrict__ BQ_task,
                            const float* __restrict__ WK_task,
                            const float* __restrict__ WQ_tm1,
                            const float* __restrict__ WQ_x,
                            const float* __restrict__ BQ,
                            const float* __restrict__ WK_x) {
    int f = threadIdx.x;
    float kA = WK_task[f] * WK_x[f];
    float sW = 0.f, sB = 0.f;
#pragma unroll
    for (int h = 0; h < 8; h++) {
        float wq = WQ_task[h * 256 + f];
        sW += wq;
        sB += wq * BQ[h * 256 + f] + BQ_task[h * 256 + f];
        g_cA[h * 256 + f] = kA * wq * WQ_tm1[h * 256 + f];
    }
    g_cB[f] = kA * WQ_x[f] * sW;
    g_cC[f] = kA * sB;
}

// ---------------- kernel 2: build Q' ----------------
__global__ void qprep_kernel(const float* __restrict__ X,
                             const float* __restrict__ prevQ) {
    int f = blockIdx.y;
    int p = blockIdx.x * 256 + threadIdx.x;
    float q = fmaf(g_cB[f], X[f * 9216 + p], g_cC[f]);
#pragma unroll
    for (int h = 0; h < 8; h++)
        q = fmaf(g_cA[h * 256 + f], prevQ[(h * 256 + f) * 9216 + p], q);
    g_Qp[f * 9216 + p] = q;
}

// ---------------- kernel 3: 3x3 conv (F=256->C=64) + affine, writes V[p][c] ----------------
__global__ void __launch_bounds__(256) conv_kernel(const float* __restrict__ X,
                                                   const float* __restrict__ Wc,
                                                   const float* __restrict__ Bc,
                                                   const float* __restrict__ WV,
                                                   const float* __restrict__ BV) {
    __shared__ float sx[4 * 294];
    __shared__ float sw[4 * 288];
    const int tid = threadIdx.x;
    const int w = blockIdx.x;
    const int cbase = blockIdx.y * 32;
    const int cl = tid >> 3;
    const int c = cbase + cl;
    const int h0 = (tid & 7) * 12;

    float acc[12];
#pragma unroll
    for (int i = 0; i < 12; i++) acc[i] = 0.f;

    for (int fc = 0; fc < 256; fc += 4) {
        __syncthreads();
        for (int i = tid; i < 4 * 294; i += 256) {
            int ff = i / 294, r = i % 294;
            int dw = r / 98, hh = r % 98;
            int ww = w + dw - 1;
            float v = 0.f;
            if (ww >= 0 && ww < 96 && hh >= 1 && hh <= 96)
                v = X[(fc + ff) * 9216 + ww * 96 + hh - 1];
            sx[i] = v;
        }
        for (int i = tid; i < 4 * 288; i += 256) {
            int ff = i / 288, r = i % 288;
            int ccl = r / 9, s = r % 9;
            sw[i] = Wc[((cbase + ccl) * 256 + fc + ff) * 9 + s];
        }
        __syncthreads();
#pragma unroll
        for (int ff = 0; ff < 4; ff++) {
            float wv[9];
#pragma unroll
            for (int s = 0; s < 9; s++) wv[s] = sw[ff * 288 + cl * 9 + s];
#pragma unroll
            for (int dw = 0; dw < 3; dw++) {
                float xr[14];
#pragma unroll
                for (int j = 0; j < 14; j++) xr[j] = sx[ff * 294 + dw * 98 + h0 + j];
#pragma unroll
                for (int hi = 0; hi < 12; hi++)
#pragma unroll
                    for (int dh = 0; dh < 3; dh++)
                        acc[hi] = fmaf(xr[hi + dh], wv[dw * 3 + dh], acc[hi]);
            }
        }
    }
    float wv_ = WV[c], bv_ = BV[c], bc_ = Bc[c];
#pragma unroll
    for (int hi = 0; hi < 12; hi++)
        g_V[(w * 96 + h0 + hi) * 64 + c] = fmaf(wv_, acc[hi] + bc_, bv_);
}

// ---------------- kernel 4: flash attention ----------------
// grid 144 (64-query tile), 512 threads = 2 engines x 256.
// engine h: key tiles kt = 2*it+h (128 keys each), it = 0..35.
// per thread QK: 4q x 8k, keys {4tx..+3} U {64+4tx..+3} (b = natural 64-bit pairs).
// smem floats: sQ 16384 | per engine: sX 2x2048 | sPT 128x68 | sVT 64x68
static const int ENG_SZ = 4096 + 8704 + 4352;                 // 17152
static const int ATTN_SMEM_BYTES = (16384 + 2 * ENG_SZ) * 4;  // 202752
static const int NC = 36 * 16;  // chunks per engine (16f x 128k each)

__device__ __forceinline__ void ldg_chunk(const float* __restrict__ X,
                                          int cc, int h, int ll, float4* rv) {
    int kt = 2 * (cc >> 4) + h;
    int fb = (cc & 15) << 4;
    int q0 = kt << 7;
#pragma unroll
    for (int t = 0; t < 2; t++) {
        int idx = ll + t * 256;
        int f = idx >> 5, s = (idx & 31) << 2;
        rv[t] = *(const float4*)(X + (fb + f) * 9216 + q0 + s);
    }
}
__device__ __forceinline__ void sts_chunk(float* dst, int ll, const float4* rv) {
#pragma unroll
    for (int t = 0; t < 2; t++) {
        int idx = ll + t * 256;
        int f = idx >> 5, s = (idx & 31) << 2;
        *(float4*)(dst + f * 128 + s) = rv[t];
    }
}

__global__ void __launch_bounds__(512, 1)
attn_kernel(const float* __restrict__ X, float* __restrict__ out) {
    extern __shared__ float sm[];
    const int tid = threadIdx.x;
    const int h = tid >> 8;
    const int ll = tid & 255;
    const int ty = ll >> 4;   // queries ty*4..+3
    const int tx = ll & 15;   // key blocks 4tx, 64+4tx; channels tx*4..+3
    const int bid = h + 1;
    const int p0 = blockIdx.x * 64;

    float* sQ = sm;
    float* eb = sm + 16384 + h * ENG_SZ;
    float* sXb[2] = { eb, eb + 2048 };
    float* sPT = eb + 4096;    // [128][68]
    float* sVT = eb + 12800;   // [64][68]

    float4 rv[2];
    ldg_chunk(X, 0, h, ll, rv);

    for (int i = tid; i < 4096; i += 512) {
        int f = i >> 4, q = (i & 15) * 4;
        *(float4*)(sQ + f * 64 + q) = *(const float4*)(g_Qp + f * 9216 + p0 + q);
    }
    __syncthreads();

    sts_chunk(sXb[0], ll, rv);
    ldg_chunk(X, 1, h, ll, rv);
    HBAR(bid);

    ULL acc2[2][4];
#pragma unroll
    for (int r = 0; r < 2; r++)
#pragma unroll
        for (int j = 0; j < 4; j++) acc2[r][j] = 0ULL;
    float m[4], lsum[4];
#pragma unroll
    for (int i = 0; i < 4; i++) { m[i] = -1e30f; lsum[i] = 0.f; }

    for (int it = 0; it < 36; it++) {
        const int q0 = (2 * it + h) * 128;

        ULL S2[4][4];
#pragma unroll
        for (int i = 0; i < 4; i++)
#pragma unroll
            for (int j = 0; j < 4; j++) S2[i][j] = 0ULL;

        // ---- QK: 16 chunks of 16 features over 128 keys ----
        for (int c16 = 0; c16 < 16; c16++) {
            const int cc = it * 16 + c16;
            if (cc + 1 < NC) sts_chunk(sXb[(cc + 1) & 1], ll, rv);
            if (cc + 2 < NC) ldg_chunk(X, cc + 2, h, ll, rv);

            const float* sQb = sQ + (c16 * 16) * 64 + ty * 4;
            const float* sXc = sXb[cc & 1] + tx * 4;
#pragma unroll
            for (int fl = 0; fl < 16; fl++) {
                float4 a4 = *(const float4*)(sQb + fl * 64);
                ULL a0 = pack2(a4.x, a4.x), a1 = pack2(a4.y, a4.y);
                ULL a2 = pack2(a4.z, a4.z), a3 = pack2(a4.w, a4.w);
                ulonglong2 b0 = *(const ulonglong2*)(sXc + fl * 128);
                ulonglong2 b1 = *(const ulonglong2*)(sXc + fl * 128 + 64);
                fma2(S2[0][0], b0.x, a0); fma2(S2[1][0], b0.x, a1);
                fma2(S2[2][0], b0.x, a2); fma2(S2[3][0], b0.x, a3);
                fma2(S2[0][1], b0.y, a0); fma2(S2[1][1], b0.y, a1);
                fma2(S2[2][1], b0.y, a2); fma2(S2[3][1], b0.y, a3);
                fma2(S2[0][2], b1.x, a0); fma2(S2[1][2], b1.x, a1);
                fma2(S2[2][2], b1.x, a2); fma2(S2[3][2], b1.x, a3);
                fma2(S2[0][3], b1.y, a0); fma2(S2[1][3], b1.y, a1);
                fma2(S2[2][3], b1.y, a2); fma2(S2[3][3], b1.y, a3);
            }
            HBAR(bid);
        }

        // ---- stage V rows 0..63 (prev PV readers done: end-of-it HBAR) ----
#pragma unroll
        for (int t = 0; t < 4; t++) {
            int idx = ll + t * 256;
            int k = idx >> 4, c4 = (idx & 15) << 2;
            *(float4*)(sVT + k * 68 + c4) = *(const float4*)(g_V + (q0 + k) * 64 + c4);
        }

        // ---- online softmax: s[q][8 keys], exp in place ----
        float s[4][8];
#pragma unroll
        for (int i = 0; i < 4; i++)
#pragma unroll
            for (int jp = 0; jp < 4; jp++)
                unpack2(S2[i][jp], s[i][2 * jp], s[i][2 * jp + 1]);

        float sc[4];
#pragma unroll
        for (int i = 0; i < 4; i++) {
            float rm = s[i][0];
#pragma unroll
            for (int j = 1; j < 8; j++) rm = fmaxf(rm, s[i][j]);
#pragma unroll
            for (int o = 8; o > 0; o >>= 1)
                rm = fmaxf(rm, __shfl_xor_sync(0xffffffffu, rm, o));
            float mn = fmaxf(m[i], rm);
            float r0 = 0.f;
#pragma unroll
            for (int j = 0; j < 8; j++) {
                s[i][j] = __expf(s[i][j] - mn);
                r0 += s[i][j];
            }
#pragma unroll
            for (int o = 8; o > 0; o >>= 1)
                r0 += __shfl_xor_sync(0xffffffffu, r0, o);
            sc[i] = __expf(m[i] - mn);
            lsum[i] = fmaf(lsum[i], sc[i], r0);
            m[i] = mn;
        }
        ULL sc2[2] = { pack2(sc[0], sc[1]), pack2(sc[2], sc[3]) };
#pragma unroll
        for (int r = 0; r < 2; r++)
#pragma unroll
            for (int j = 0; j < 4; j++) mul2(acc2[r][j], sc2[r]);

        // ---- write P transposed: rows 4tx+j and 64+4tx+j ----
#pragma unroll
        for (int j = 0; j < 4; j++) {
            float4 v = make_float4(s[0][j], s[1][j], s[2][j], s[3][j]);
            *(float4*)(sPT + (tx * 4 + j) * 68 + ty * 4) = v;
        }
#pragma unroll
        for (int j = 0; j < 4; j++) {
            float4 v = make_float4(s[0][4 + j], s[1][4 + j], s[2][4 + j], s[3][4 + j]);
            *(float4*)(sPT + (64 + tx * 4 + j) * 68 + ty * 4) = v;
        }
        HBAR(bid);  // sPT + sVT(pass0) ready

        // ---- PV pass 0: keys 0..63 ----
#pragma unroll 8
        for (int k = 0; k < 64; k++) {
            ulonglong2 pp = *(const ulonglong2*)(sPT + k * 68 + ty * 4);
            float4 v = *(const float4*)(sVT + k * 68 + tx * 4);
            ULL v0 = pack2(v.x, v.x), v1 = pack2(v.y, v.y);
            ULL v2 = pack2(v.z, v.z), v3 = pack2(v.w, v.w);
            fma2(acc2[0][0], pp.x, v0); fma2(acc2[1][0], pp.y, v0);
            fma2(acc2[0][1], pp.x, v1); fma2(acc2[1][1], pp.y, v1);
            fma2(acc2[0][2], pp.x, v2); fma2(acc2[1][2], pp.y, v2);
            fma2(acc2[0][3], pp.x, v3); fma2(acc2[1][3], pp.y, v3);
        }
        HBAR(bid);  // sVT pass0 readers done

        // ---- stage V rows 64..127 ----
#pragma unroll
        for (int t = 0; t < 4; t++) {
            int idx = ll + t * 256;
            int k = idx >> 4, c4 = (idx & 15) << 2;
            *(float4*)(sVT + k * 68 + c4) =
                *(const float4*)(g_V + (q0 + 64 + k) * 64 + c4);
        }
        HBAR(bid);  // sVT pass1 ready

        // ---- PV pass 1: keys 64..127 ----
#pragma unroll 8
        for (int k = 0; k < 64; k++) {
            ulonglong2 pp = *(const ulonglong2*)(sPT + (64 + k) * 68 + ty * 4);
            float4 v = *(const float4*)(sVT + k * 68 + tx * 4);
            ULL v0 = pack2(v.x, v.x), v1 = pack2(v.y, v.y);
            ULL v2 = pack2(v.z, v.z), v3 = pack2(v.w, v.w);
            fma2(acc2[0][0], pp.x, v0); fma2(acc2[1][0], pp.y, v0);
            fma2(acc2[0][1], pp.x, v1); fma2(acc2[1][1], pp.y, v1);
            fma2(acc2[0][2], pp.x, v2); fma2(acc2[1][2], pp.y, v2);
            fma2(acc2[0][3], pp.x, v3); fma2(acc2[1][3], pp.y, v3);
        }
        HBAR(bid);  // end-of-it: protects sPT/sVT/sX reuse
    }

    // ---- epilogue: merge the two flash states ----
    __syncthreads();
    float* ex = sm;  // reuse sQ: 256 threads * 24 floats
    if (h == 1) {
        float* b = ex + ll * 24;
#pragma unroll
        for (int i = 0; i < 4; i++) { b[i] = m[i]; b[4 + i] = lsum[i]; }
#pragma unroll
        for (int r = 0; r < 2; r++)
#pragma unroll
            for (int j = 0; j < 4; j++) {
                float lo, hi;
                unpack2(acc2[r][j], lo, hi);
                b[8 + (r * 4 + j) * 2] = lo;
                b[9 + (r * 4 + j) * 2] = hi;
            }
    }
    __syncthreads();
    if (h == 0) {
        const float* b = ex + ll * 24;
        float w0[4], w1[4], L[4];
#pragma unroll
        for (int i = 0; i < 4; i++) {
            float M = fmaxf(m[i], b[i]);
            w0[i] = __expf(m[i] - M);
            w1[i] = __expf(b[i] - M);
            L[i] = lsum[i] * w0[i] + b[4 + i] * w1[i];
        }
#pragma unroll
        for (int r = 0; r < 2; r++)
#pragma unroll
            for (int j = 0; j < 4; j++) {
                float lo, hi;
                unpack2(acc2[r][j], lo, hi);
                float p1lo = b[8 + (r * 4 + j) * 2];
                float p1hi = b[9 + (r * 4 + j) * 2];
                int i0 = 2 * r, i1 = 2 * r + 1;
                int cc = tx * 4 + j;
                out[cc * 9216 + p0 + ty * 4 + i0] = (lo * w0[i0] + p1lo * w1[i0]) / L[i0];
                out[cc * 9216 + p0 + ty * 4 + i1] = (hi * w0[i1] + p1hi * w1[i1]) / L[i1];
            }
    }
}

// ---------------- launch ----------------
extern "C" void kernel_launch(void* const* d_in, const int* in_sizes, int n_in,
                              void* d_out, int out_size) {
    const float* X        = (const float*)d_in[0];
    const float* WQ_task  = (const float*)d_in[1];
    const float* BQ_task  = (const float*)d_in[2];
    const float* WK_task  = (const float*)d_in[3];
    // d_in[4]=BK_task, d_in[11]=BK: row-constant in logits -> cancel in softmax
    const float* WV_task  = (const float*)d_in[5];
    const float* BV_task  = (const float*)d_in[6];
    const float* WQ_tm1   = (const float*)d_in[7];
    const float* WQ_x     = (const float*)d_in[8];
    const float* BQ       = (const float*)d_in[9];
    const float* WK_x     = (const float*)d_in[10];
    const float* prevQ    = (const float*)d_in[12];
    const float* Vconv_w  = (const float*)d_in[13];
    const float* Vconv_b  = (const float*)d_in[14];
    float* out = (float*)d_out;

    coef_kernel<<<1, 256>>>(WQ_task, BQ_task, WK_task, WQ_tm1, WQ_x, BQ, WK_x);
    qprep_kernel<<<dim3(36, 256), 256>>>(X, prevQ);
    conv_kernel<<<dim3(96, 2), 256>>>(X, Vconv_w, Vconv_b, WV_task, BV_task);

    cudaFuncSetAttribute(attn_kernel,
                         cudaFuncAttributeMaxDynamicSharedMemorySize,
                         ATTN_SMEM_BYTES);
    attn_kernel<<<144, 512, ATTN_SMEM_BYTES>>>(X, out);
}